// round 6
// baseline (speedup 1.0000x reference)
#include <cuda_runtime.h>
#include <cuda_bf16.h>
#include <cstdint>

#define VOCAB 50000
#define NQUADS 4096                 // NCELLS/4 cell-quads (4 cells per warp)
#define GRID 148
#define THREADS 1024
#define NWARPS_TOTAL (GRID * 32)    // 4736
#define ROWPAIRS (VOCAB / 2)        // 25000
#define TABLE_BYTES (VOCAB * 4)     // 200000

__device__ float g_proj[VOCAB];
__device__ unsigned g_ctr;          // grid-barrier counter (monotonic across replays)

__global__ void __launch_bounds__(THREADS, 1) fused_kernel(
    const int*   __restrict__ x,
    const float* __restrict__ E,
    const float* __restrict__ W,
    const float* __restrict__ bias,
    float*       __restrict__ out)
{
    extern __shared__ float s_proj[];    // 200000 B table

    int tid   = threadIdx.x;
    int lane  = tid & 31;
    int wid   = tid >> 5;
    int gwarp = blockIdx.x * 32 + wid;   // 0..4735

    // ---- early independent loads: tokens + bias (hide DRAM latency under phase A)
    int4 t = make_int4(0, 0, 0, 0);
    if (gwarp < NQUADS)
        t = reinterpret_cast<const int4*>(x)[gwarp * 32 + lane];
    float bv = bias[0];

    // ================= Phase A: p[v] = dot(E[v,:], W) =================
    {
        const float4* __restrict__ e4 = reinterpret_cast<const float4*>(E);
        const float4* __restrict__ w4 = reinterpret_cast<const float4*>(W);
        float4 wa = w4[lane];
        float4 wb = w4[lane + 32];

        for (int q = gwarp; q < ROWPAIRS; q += NWARPS_TOTAL) {
            int row0 = q * 2;
            float4 a0 = e4[(size_t)row0 * 64 + lane];
            float4 a1 = e4[(size_t)row0 * 64 + lane + 32];
            float4 b0 = e4[(size_t)(row0 + 1) * 64 + lane];
            float4 b1 = e4[(size_t)(row0 + 1) * 64 + lane + 32];

            float s0 = 0.f, s1 = 0.f;
            s0 = fmaf(a0.x, wa.x, s0); s0 = fmaf(a0.y, wa.y, s0);
            s0 = fmaf(a0.z, wa.z, s0); s0 = fmaf(a0.w, wa.w, s0);
            s0 = fmaf(a1.x, wb.x, s0); s0 = fmaf(a1.y, wb.y, s0);
            s0 = fmaf(a1.z, wb.z, s0); s0 = fmaf(a1.w, wb.w, s0);
            s1 = fmaf(b0.x, wa.x, s1); s1 = fmaf(b0.y, wa.y, s1);
            s1 = fmaf(b0.z, wa.z, s1); s1 = fmaf(b0.w, wa.w, s1);
            s1 = fmaf(b1.x, wb.x, s1); s1 = fmaf(b1.y, wb.y, s1);
            s1 = fmaf(b1.z, wb.z, s1); s1 = fmaf(b1.w, wb.w, s1);

            #pragma unroll
            for (int o = 16; o > 0; o >>= 1) {
                s0 += __shfl_xor_sync(0xFFFFFFFFu, s0, o);
                s1 += __shfl_xor_sync(0xFFFFFFFFu, s1, o);
            }
            if (lane == 0) {
                g_proj[row0]     = s0;
                g_proj[row0 + 1] = s1;
            }
        }
    }

    // ================= Grid barrier (1 block/SM -> single wave, no deadlock) ====
    __syncthreads();
    if (tid == 0) {
        unsigned old;
        // release-arrive: publishes this block's g_proj stores (block-ordered by
        // the __syncthreads above) to gpu scope
        asm volatile("atom.add.release.gpu.u32 %0, [%1], %2;"
                     : "=r"(old) : "l"(&g_ctr), "r"(1u) : "memory");
        unsigned target = old - (old % (unsigned)GRID) + (unsigned)GRID;
        unsigned cur;
        do {
            asm volatile("ld.acquire.gpu.u32 %0, [%1];"
                         : "=r"(cur) : "l"(&g_ctr) : "memory");
        } while (cur < target);
    }
    __syncthreads();

    // ================= Phase B: stage table to smem, gather, reduce =============
    {
        uint32_t sbase = (uint32_t)__cvta_generic_to_shared(s_proj);
        const float4* __restrict__ g4 = reinterpret_cast<const float4*>(g_proj);
        for (int i = tid; i < VOCAB / 4; i += THREADS) {
            asm volatile("cp.async.cg.shared.global [%0], [%1], 16;"
                         :: "r"(sbase + i * 16), "l"(g4 + i));
        }
        asm volatile("cp.async.commit_group;");
        asm volatile("cp.async.wait_group 0;" ::: "memory");
    }
    __syncthreads();

    if (gwarp < NQUADS) {
        float s = s_proj[t.x] + s_proj[t.y] + s_proj[t.z] + s_proj[t.w];
        s += __shfl_xor_sync(0xFFFFFFFFu, s, 4);
        s += __shfl_xor_sync(0xFFFFFFFFu, s, 2);
        s += __shfl_xor_sync(0xFFFFFFFFu, s, 1);
        if ((lane & 7) == 0) out[gwarp * 4 + (lane >> 3)] = s + bv;
    }
}

extern "C" void kernel_launch(void* const* d_in, const int* in_sizes, int n_in,
                              void* d_out, int out_size)
{
    const int*   x = (const int*)  d_in[0];
    const float* E = (const float*)d_in[1];
    const float* W = (const float*)d_in[2];
    const float* b = (const float*)d_in[3];
    float* out = (float*)d_out;

    static bool attr_done = false;
    if (!attr_done) {
        cudaFuncSetAttribute(fused_kernel,
                             cudaFuncAttributeMaxDynamicSharedMemorySize,
                             TABLE_BYTES);
        attr_done = true;
    }

    fused_kernel<<<GRID, THREADS, TABLE_BYTES>>>(x, E, W, b, out);
}

// round 7
// speedup vs baseline: 1.0025x; 1.0025x over previous
#include <cuda_runtime.h>
#include <cuda_bf16.h>
#include <cstdint>

#define VOCAB   50000
#define NCELLS  16384
#define NQUADS  4096            // 4 cells per quad, 8 int4 tokens each
#define GROUPS  4
#define BLK_PER_GRP 37          // 4 * 37 = 148 blocks
#define SLICE   (VOCAB / GROUPS)        // 12500 vocab entries per group
#define SLICE_BYTES (SLICE * 4)         // 50000 B smem
#define GT      512             // gather threads/block (16 warps)
#define MAXQ    7               // max quads per warp: ceil(4096/37/16)=7

__device__ float g_proj[VOCAB];

// ---------------------------------------------------------------------------
// Kernel 1: p[v] = dot(E[v,:], W), 4 rows/warp, 8 outstanding LDG.128/thread.
// Blocks 0..63 also zero out[] (gather accumulates atomically).
// Signals PDL so gather's x-prefetch overlaps this kernel's tail.
// ---------------------------------------------------------------------------
__global__ void __launch_bounds__(256) proj_kernel(
    const float* __restrict__ E,
    const float* __restrict__ W,
    float*       __restrict__ out)
{
    int gwarp = (blockIdx.x * blockDim.x + threadIdx.x) >> 5;
    int lane  = threadIdx.x & 31;
    int row0  = gwarp * 4;

    // zero the output (64 blocks x 256 threads = 16384)
    if (blockIdx.x < 64)
        out[blockIdx.x * 256 + threadIdx.x] = 0.0f;

    if (row0 < VOCAB) {
        const float4* __restrict__ e4 = reinterpret_cast<const float4*>(E);
        const float4* __restrict__ w4 = reinterpret_cast<const float4*>(W);

        float4 wa = w4[lane];
        float4 wb = w4[lane + 32];

        float4 r0a = e4[(size_t)(row0 + 0) * 64 + lane];
        float4 r0b = e4[(size_t)(row0 + 0) * 64 + lane + 32];
        float4 r1a = e4[(size_t)(row0 + 1) * 64 + lane];
        float4 r1b = e4[(size_t)(row0 + 1) * 64 + lane + 32];
        float4 r2a = e4[(size_t)(row0 + 2) * 64 + lane];
        float4 r2b = e4[(size_t)(row0 + 2) * 64 + lane + 32];
        float4 r3a = e4[(size_t)(row0 + 3) * 64 + lane];
        float4 r3b = e4[(size_t)(row0 + 3) * 64 + lane + 32];

        float s0 = 0.f, s1 = 0.f, s2 = 0.f, s3 = 0.f;
        s0 = fmaf(r0a.x, wa.x, s0); s0 = fmaf(r0a.y, wa.y, s0);
        s0 = fmaf(r0a.z, wa.z, s0); s0 = fmaf(r0a.w, wa.w, s0);
        s0 = fmaf(r0b.x, wb.x, s0); s0 = fmaf(r0b.y, wb.y, s0);
        s0 = fmaf(r0b.z, wb.z, s0); s0 = fmaf(r0b.w, wb.w, s0);

        s1 = fmaf(r1a.x, wa.x, s1); s1 = fmaf(r1a.y, wa.y, s1);
        s1 = fmaf(r1a.z, wa.z, s1); s1 = fmaf(r1a.w, wa.w, s1);
        s1 = fmaf(r1b.x, wb.x, s1); s1 = fmaf(r1b.y, wb.y, s1);
        s1 = fmaf(r1b.z, wb.z, s1); s1 = fmaf(r1b.w, wb.w, s1);

        s2 = fmaf(r2a.x, wa.x, s2); s2 = fmaf(r2a.y, wa.y, s2);
        s2 = fmaf(r2a.z, wa.z, s2); s2 = fmaf(r2a.w, wa.w, s2);
        s2 = fmaf(r2b.x, wb.x, s2); s2 = fmaf(r2b.y, wb.y, s2);
        s2 = fmaf(r2b.z, wb.z, s2); s2 = fmaf(r2b.w, wb.w, s2);

        s3 = fmaf(r3a.x, wa.x, s3); s3 = fmaf(r3a.y, wa.y, s3);
        s3 = fmaf(r3a.z, wa.z, s3); s3 = fmaf(r3a.w, wa.w, s3);
        s3 = fmaf(r3b.x, wb.x, s3); s3 = fmaf(r3b.y, wb.y, s3);
        s3 = fmaf(r3b.z, wb.z, s3); s3 = fmaf(r3b.w, wb.w, s3);

        #pragma unroll
        for (int o = 16; o > 0; o >>= 1) {
            s0 += __shfl_xor_sync(0xFFFFFFFFu, s0, o);
            s1 += __shfl_xor_sync(0xFFFFFFFFu, s1, o);
            s2 += __shfl_xor_sync(0xFFFFFFFFu, s2, o);
            s3 += __shfl_xor_sync(0xFFFFFFFFu, s3, o);
        }
        if (lane == 0) {
            g_proj[row0 + 0] = s0;
            g_proj[row0 + 1] = s1;
            g_proj[row0 + 2] = s2;
            g_proj[row0 + 3] = s3;
        }
    }

    asm volatile("griddepcontrol.launch_dependents;" ::: "memory");
}

// ---------------------------------------------------------------------------
// Kernel 2: partitioned gather. 148 blocks = 4 groups x 37 blocks.
// Group g stages vocab slice [g*12500, (g+1)*12500) into 50 KB smem.
// Each warp prefetches up to 7 x-quads into registers BEFORE
// griddepcontrol.wait (overlaps proj), then gathers in-slice tokens and
// atomicAdds per-cell partials. Group 0 contributes the bias.
// ---------------------------------------------------------------------------
__global__ void __launch_bounds__(GT) gather_kernel(
    const int*   __restrict__ x,
    const float* __restrict__ bias,
    float*       __restrict__ out)
{
    extern __shared__ float s_slice[];   // SLICE floats

    int tid  = threadIdx.x;
    int lane = tid & 31;
    int wid  = tid >> 5;                 // 0..15
    int grp  = blockIdx.x / BLK_PER_GRP; // 0..3
    int bl   = blockIdx.x % BLK_PER_GRP; // 0..36
    int base = grp * SLICE;

    // ---- prolog (independent of proj): prefetch tokens + bias ----
    const int4* __restrict__ x4 = reinterpret_cast<const int4*>(x);
    int4 tq[MAXQ];
    #pragma unroll
    for (int i = 0; i < MAXQ; ++i) {
        int q = bl + BLK_PER_GRP * (wid + 16 * i);
        if (q < NQUADS) tq[i] = x4[q * 32 + lane];
    }
    float bv = (grp == 0) ? bias[0] : 0.0f;

    // ---- wait for proj's g_proj + out zeroing to be visible ----
    asm volatile("griddepcontrol.wait;" ::: "memory");

    // ---- stage this group's 50 KB slice ----
    {
        uint32_t sbase = (uint32_t)__cvta_generic_to_shared(s_slice);
        const float4* __restrict__ g4 =
            reinterpret_cast<const float4*>(g_proj + base);
        for (int i = tid; i < SLICE / 4; i += GT) {
            asm volatile("cp.async.cg.shared.global [%0], [%1], 16;"
                         :: "r"(sbase + i * 16), "l"(g4 + i));
        }
        asm volatile("cp.async.commit_group;");
        asm volatile("cp.async.wait_group 0;" ::: "memory");
    }
    __syncthreads();

    // ---- gather in-slice tokens, 8-lane reduce, atomic accumulate ----
    #pragma unroll
    for (int i = 0; i < MAXQ; ++i) {
        int q = bl + BLK_PER_GRP * (wid + 16 * i);
        if (q >= NQUADS) break;

        int4 t = tq[i];
        float s = 0.0f;
        unsigned i0 = (unsigned)(t.x - base);
        unsigned i1 = (unsigned)(t.y - base);
        unsigned i2 = (unsigned)(t.z - base);
        unsigned i3 = (unsigned)(t.w - base);
        if (i0 < (unsigned)SLICE) s += s_slice[i0];
        if (i1 < (unsigned)SLICE) s += s_slice[i1];
        if (i2 < (unsigned)SLICE) s += s_slice[i2];
        if (i3 < (unsigned)SLICE) s += s_slice[i3];

        s += __shfl_xor_sync(0xFFFFFFFFu, s, 4);
        s += __shfl_xor_sync(0xFFFFFFFFu, s, 2);
        s += __shfl_xor_sync(0xFFFFFFFFu, s, 1);

        if ((lane & 7) == 0)
            atomicAdd(&out[q * 4 + (lane >> 3)], s + bv);
    }
}

extern "C" void kernel_launch(void* const* d_in, const int* in_sizes, int n_in,
                              void* d_out, int out_size)
{
    const int*   x = (const int*)  d_in[0];
    const float* E = (const float*)d_in[1];
    const float* W = (const float*)d_in[2];
    const float* b = (const float*)d_in[3];
    float* out = (float*)d_out;

    static bool attr_done = false;
    if (!attr_done) {
        cudaFuncSetAttribute(gather_kernel,
                             cudaFuncAttributeMaxDynamicSharedMemorySize,
                             SLICE_BYTES);
        attr_done = true;
    }

    // proj: 12500 row-quads, 8 warps/block -> 1563 blocks
    proj_kernel<<<(VOCAB / 4 + 7) / 8, 256>>>(E, W, out);

    // gather: 148 blocks x 512 threads, PDL so its prolog overlaps proj
    cudaLaunchConfig_t cfg = {};
    cfg.gridDim          = dim3(GROUPS * BLK_PER_GRP, 1, 1);
    cfg.blockDim         = dim3(GT, 1, 1);
    cfg.dynamicSmemBytes = SLICE_BYTES;
    cfg.stream           = 0;
    cudaLaunchAttribute attrs[1];
    attrs[0].id = cudaLaunchAttributeProgrammaticStreamSerialization;
    attrs[0].val.programmaticStreamSerializationAllowed = 1;
    cfg.attrs    = attrs;
    cfg.numAttrs = 1;
    cudaLaunchKernelEx(&cfg, gather_kernel, x, b, out);
}